// round 7
// baseline (speedup 1.0000x reference)
#include <cuda_runtime.h>
#include <cstdint>

#define T_TOK 8192
#define DDIM  1024
#define FDIM  4096
#define NEXP  8

#define BM 128
#define BN 64
#define BK 32
#define STAGES 3

#define A_PITCH (BK + 4)      // 36 words; conflict-free A-fragment banks
#define B_PITCH (BN + 8)      // 72 words; conflict-free B-fragment banks
#define A_STAGE (BM * A_PITCH)
#define B_STAGE (BK * B_PITCH)

// ---------------- scratch (no allocations allowed) ----------------
__device__ int   g_counts[NEXP];
__device__ int   g_offsets[NEXP];
__device__ int   g_cur[NEXP];
__device__ int   g_top_idx[T_TOK * 2];
__device__ float g_top_w[T_TOK * 2];
__device__ int   g_slot_tok[T_TOK * 2];
__device__ float g_slot_w[T_TOK * 2];
__device__ float g_h[(size_t)T_TOK * 2 * FDIM];   // 268 MB hidden scratch

// ---------------- helpers ----------------
__device__ __forceinline__ void mma_tf32(float* c, const uint32_t* a, uint32_t b0, uint32_t b1) {
    asm volatile(
        "mma.sync.aligned.m16n8k8.row.col.f32.tf32.tf32.f32 "
        "{%0,%1,%2,%3}, {%4,%5,%6,%7}, {%8,%9}, {%0,%1,%2,%3};\n"
        : "+f"(c[0]), "+f"(c[1]), "+f"(c[2]), "+f"(c[3])
        : "r"(a[0]), "r"(a[1]), "r"(a[2]), "r"(a[3]), "r"(b0), "r"(b1));
}

// 3xTF32 split: x = hi + lo; residual computed with explicit sub.rn so the
// Sterbenz-exact cancellation can never be broken by fast-math contraction.
__device__ __forceinline__ void split_tf32(float x, uint32_t& hi, uint32_t& lo) {
    asm("cvt.rna.tf32.f32 %0, %1;" : "=r"(hi) : "f"(x));
    float r;
    asm("sub.rn.f32 %0, %1, %2;" : "=f"(r) : "f"(x), "f"(__uint_as_float(hi)));
    asm("cvt.rna.tf32.f32 %0, %1;" : "=r"(lo) : "f"(r));
}

__device__ __forceinline__ void cp16(uint32_t dst, const void* src, bool valid) {
    int sz = valid ? 16 : 0;
    asm volatile("cp.async.cg.shared.global [%0], [%1], 16, %2;\n"
                 :: "r"(dst), "l"(src), "r"(sz));
}
#define CP_COMMIT() asm volatile("cp.async.commit_group;\n" ::: "memory")
#define CP_WAIT1()  asm volatile("cp.async.wait_group 1;\n" ::: "memory")

// ---------------- gating ----------------
__global__ void zero_counts_kernel() {
    if (threadIdx.x < NEXP) g_counts[threadIdx.x] = 0;
}

__global__ void gate_kernel(const float* __restrict__ x, const float* __restrict__ gw) {
    int warp = (blockIdx.x * blockDim.x + threadIdx.x) >> 5;
    int lane = threadIdx.x & 31;
    if (warp >= T_TOK) return;
    const float* xr = x + (size_t)warp * DDIM;

    float acc[NEXP];
#pragma unroll
    for (int e = 0; e < NEXP; e++) acc[e] = 0.f;

    for (int i = lane; i < DDIM; i += 32) {
        float xv = xr[i];
        const float* g = gw + i * NEXP;
#pragma unroll
        for (int e = 0; e < NEXP; e++) acc[e] += xv * g[e];
    }
#pragma unroll
    for (int e = 0; e < NEXP; e++) {
#pragma unroll
        for (int o = 16; o > 0; o >>= 1) acc[e] += __shfl_xor_sync(0xFFFFFFFFu, acc[e], o);
    }
    if (lane == 0) {
        int i0 = 0; float l0 = acc[0];
#pragma unroll
        for (int e = 1; e < NEXP; e++) if (acc[e] > l0) { l0 = acc[e]; i0 = e; }
        int i1 = -1; float l1 = -1e30f;
#pragma unroll
        for (int e = 0; e < NEXP; e++) if (e != i0 && acc[e] > l1) { l1 = acc[e]; i1 = e; }
        float w0 = 1.f / (1.f + __expf(l1 - l0));
        float w1 = 1.f - w0;
        g_top_idx[2 * warp + 0] = i0;
        g_top_idx[2 * warp + 1] = i1;
        g_top_w[2 * warp + 0] = w0;
        g_top_w[2 * warp + 1] = w1;
        atomicAdd(&g_counts[i0], 1);
        atomicAdd(&g_counts[i1], 1);
    }
}

__global__ void scan_kernel() {
    if (threadIdx.x == 0 && blockIdx.x == 0) {
        int s = 0;
        for (int e = 0; e < NEXP; e++) {
            g_offsets[e] = s;
            g_cur[e] = s;
            s += g_counts[e];
        }
    }
}

__global__ void place_kernel() {
    int t = blockIdx.x * blockDim.x + threadIdx.x;
    if (t >= T_TOK) return;
#pragma unroll
    for (int k = 0; k < 2; k++) {
        int e = g_top_idx[2 * t + k];
        int slot = atomicAdd(&g_cur[e], 1);
        g_slot_tok[slot] = t;
        g_slot_w[slot] = g_top_w[2 * t + k];
    }
}

// ---------------- Phase A: h = silu(X@w1)*(X@w3) * route_w ----------------
#define G13_SMEM_BYTES ((STAGES * (A_STAGE + 2 * B_STAGE)) * 4 + BM * 8)

__global__ void __launch_bounds__(256) gemm13_kernel(const float* __restrict__ x,
                                                     const float* __restrict__ w1,
                                                     const float* __restrict__ w3) {
    int e = blockIdx.z;
    int count = g_counts[e];
    int m0 = blockIdx.y * BM;
    if (m0 >= count) return;
    int base = g_offsets[e];
    int n0 = blockIdx.x * BN;

    extern __shared__ uint32_t sm[];
    uint32_t* As = sm;                               // STAGES * A_STAGE
    uint32_t* B1 = sm + STAGES * A_STAGE;            // STAGES * B_STAGE
    uint32_t* B3 = B1 + STAGES * B_STAGE;            // STAGES * B_STAGE
    int*   s_tok = (int*)(B3 + STAGES * B_STAGE);
    float* s_w   = (float*)(s_tok + BM);

    uint32_t sa_As = (uint32_t)__cvta_generic_to_shared(As);
    uint32_t sa_B1 = (uint32_t)__cvta_generic_to_shared(B1);
    uint32_t sa_B3 = (uint32_t)__cvta_generic_to_shared(B3);

    int tid = threadIdx.x;
    int lane = tid & 31;
    int wid = tid >> 5;
    int wm = (wid >> 1) * 32;
    int wn = (wid & 1) * 32;

    if (tid < BM) {
        int m = m0 + tid;
        if (m < count) {
            s_tok[tid] = g_slot_tok[base + m];
            s_w[tid] = g_slot_w[base + m];
        } else {
            s_tok[tid] = -1;
            s_w[tid] = 0.f;
        }
    }
    __syncthreads();

    const float* W1 = w1 + (size_t)e * DDIM * FDIM;
    const float* W3 = w3 + (size_t)e * DDIM * FDIM;

    int a_row[4], a_kk[4], a_tok[4];
#pragma unroll
    for (int j = 0; j < 4; j++) {
        int cid = tid + j * 256;
        a_row[j] = cid >> 3;
        a_kk[j] = (cid & 7) * 4;
        a_tok[j] = s_tok[a_row[j]];
    }
    int b_r[2], b_c[2];
#pragma unroll
    for (int j = 0; j < 2; j++) {
        int cid = tid + j * 256;
        b_r[j] = cid >> 4;
        b_c[j] = (cid & 15) * 4;
    }

    float acc1[2][4][4];
    float acc2[2][4][4];
#pragma unroll
    for (int mt = 0; mt < 2; mt++)
#pragma unroll
        for (int nt = 0; nt < 4; nt++)
#pragma unroll
            for (int i = 0; i < 4; i++) { acc1[mt][nt][i] = 0.f; acc2[mt][nt][i] = 0.f; }

    const int KT = DDIM / BK;

    auto issue = [&](int s, int k0) {
#pragma unroll
        for (int j = 0; j < 4; j++) {
            int t = a_tok[j];
            const float* src = (t >= 0) ? x + (size_t)t * DDIM + k0 + a_kk[j] : x;
            cp16(sa_As + (uint32_t)((s * A_STAGE + a_row[j] * A_PITCH + a_kk[j]) * 4), src, t >= 0);
        }
#pragma unroll
        for (int j = 0; j < 2; j++) {
            size_t off = (size_t)(k0 + b_r[j]) * FDIM + n0 + b_c[j];
            uint32_t sd = (uint32_t)((s * B_STAGE + b_r[j] * B_PITCH + b_c[j]) * 4);
            cp16(sa_B1 + sd, W1 + off, true);
            cp16(sa_B3 + sd, W3 + off, true);
        }
        CP_COMMIT();
    };

    issue(0, 0);
    issue(1, BK);

    for (int kt = 0; kt < KT; kt++) {
        CP_WAIT1();            // stage kt resident
        __syncthreads();       // everyone done reading stage kt-1
        if (kt + 2 < KT) issue((kt + 2) % STAGES, (kt + 2) * BK);  // overwrites stage kt-1: safe
        else             CP_COMMIT();

        int st = kt % STAGES;
        const uint32_t* Ac = As + st * A_STAGE;
        const uint32_t* B1c = B1 + st * B_STAGE;
        const uint32_t* B3c = B3 + st * B_STAGE;

#pragma unroll
        for (int kk = 0; kk < BK; kk += 8) {
            uint32_t ahi[2][4], alo[2][4];
#pragma unroll
            for (int mt = 0; mt < 2; mt++) {
                int r = wm + mt * 16 + (lane >> 2);
                int c = kk + (lane & 3);
                split_tf32(__uint_as_float(Ac[r * A_PITCH + c]),           ahi[mt][0], alo[mt][0]);
                split_tf32(__uint_as_float(Ac[(r + 8) * A_PITCH + c]),     ahi[mt][1], alo[mt][1]);
                split_tf32(__uint_as_float(Ac[r * A_PITCH + c + 4]),       ahi[mt][2], alo[mt][2]);
                split_tf32(__uint_as_float(Ac[(r + 8) * A_PITCH + c + 4]), ahi[mt][3], alo[mt][3]);
            }
#pragma unroll
            for (int nt = 0; nt < 4; nt++) {
                int br = kk + (lane & 3);
                int bc = wn + nt * 8 + (lane >> 2);
                uint32_t b1h0, b1l0, b1h1, b1l1, b3h0, b3l0, b3h1, b3l1;
                split_tf32(__uint_as_float(B1c[br * B_PITCH + bc]),       b1h0, b1l0);
                split_tf32(__uint_as_float(B1c[(br + 4) * B_PITCH + bc]), b1h1, b1l1);
                split_tf32(__uint_as_float(B3c[br * B_PITCH + bc]),       b3h0, b3l0);
                split_tf32(__uint_as_float(B3c[(br + 4) * B_PITCH + bc]), b3h1, b3l1);
#pragma unroll
                for (int mt = 0; mt < 2; mt++) {
                    mma_tf32(acc1[mt][nt], ahi[mt], b1h0, b1h1);
                    mma_tf32(acc1[mt][nt], alo[mt], b1h0, b1h1);
                    mma_tf32(acc1[mt][nt], ahi[mt], b1l0, b1l1);
                    mma_tf32(acc2[mt][nt], ahi[mt], b3h0, b3h1);
                    mma_tf32(acc2[mt][nt], alo[mt], b3h0, b3h1);
                    mma_tf32(acc2[mt][nt], ahi[mt], b3l0, b3l1);
                }
            }
        }
    }

    // epilogue: SwiGLU * routing weight -> g_h
#pragma unroll
    for (int mt = 0; mt < 2; mt++) {
#pragma unroll
        for (int nt = 0; nt < 4; nt++) {
            int r0 = wm + mt * 16 + (lane >> 2);
            int col = n0 + wn + nt * 8 + (lane & 3) * 2;
#pragma unroll
            for (int half = 0; half < 2; half++) {
                int r = r0 + half * 8;
                int m = m0 + r;
                if (m < count) {
                    float u0 = acc1[mt][nt][half * 2 + 0];
                    float u1 = acc1[mt][nt][half * 2 + 1];
                    float v0 = acc2[mt][nt][half * 2 + 0];
                    float v1 = acc2[mt][nt][half * 2 + 1];
                    float wr = s_w[r];
                    float h0 = (u0 / (1.f + __expf(-u0))) * v0 * wr;
                    float h1 = (u1 / (1.f + __expf(-u1))) * v1 * wr;
                    float2* p = (float2*)(g_h + (size_t)(base + m) * FDIM + col);
                    *p = make_float2(h0, h1);
                }
            }
        }
    }
}

// ---------------- Phase B: out += h @ w2 (atomic scatter) ----------------
#define G2_SMEM_BYTES ((STAGES * (A_STAGE + B_STAGE)) * 4 + BM * 4)

__global__ void __launch_bounds__(256) gemm2_kernel(const float* __restrict__ w2,
                                                    float* __restrict__ out) {
    int e = blockIdx.z;
    int count = g_counts[e];
    int m0 = blockIdx.y * BM;
    if (m0 >= count) return;
    int base = g_offsets[e];
    int n0 = blockIdx.x * BN;

    extern __shared__ uint32_t sm[];
    uint32_t* As = sm;
    uint32_t* Bs = sm + STAGES * A_STAGE;
    int* s_tok = (int*)(Bs + STAGES * B_STAGE);

    uint32_t sa_As = (uint32_t)__cvta_generic_to_shared(As);
    uint32_t sa_Bs = (uint32_t)__cvta_generic_to_shared(Bs);

    int tid = threadIdx.x;
    int lane = tid & 31;
    int wid = tid >> 5;
    int wm = (wid >> 1) * 32;
    int wn = (wid & 1) * 32;

    if (tid < BM) {
        int m = m0 + tid;
        s_tok[tid] = (m < count) ? g_slot_tok[base + m] : -1;
    }
    __syncthreads();

    const float* W2 = w2 + (size_t)e * FDIM * DDIM;

    int a_row[4], a_kk[4]; bool a_ok[4];
#pragma unroll
    for (int j = 0; j < 4; j++) {
        int cid = tid + j * 256;
        a_row[j] = cid >> 3;
        a_kk[j] = (cid & 7) * 4;
        a_ok[j] = (m0 + a_row[j]) < count;
    }
    int b_r[2], b_c[2];
#pragma unroll
    for (int j = 0; j < 2; j++) {
        int cid = tid + j * 256;
        b_r[j] = cid >> 4;
        b_c[j] = (cid & 15) * 4;
    }

    float acc[2][4][4];
#pragma unroll
    for (int mt = 0; mt < 2; mt++)
#pragma unroll
        for (int nt = 0; nt < 4; nt++)
#pragma unroll
            for (int i = 0; i < 4; i++) acc[mt][nt][i] = 0.f;

    const int KT = FDIM / BK;

    auto issue = [&](int s, int k0) {
#pragma unroll
        for (int j = 0; j < 4; j++) {
            const float* src = g_h + (size_t)(base + m0 + a_row[j]) * FDIM + k0 + a_kk[j];
            cp16(sa_As + (uint32_t)((s * A_STAGE + a_row[j] * A_PITCH + a_kk[j]) * 4),
                 a_ok[j] ? src : (const float*)g_h, a_ok[j]);
        }
#pragma unroll
        for (int j = 0; j < 2; j++) {
            size_t off = (size_t)(k0 + b_r[j]) * DDIM + n0 + b_c[j];
            cp16(sa_Bs + (uint32_t)((s * B_STAGE + b_r[j] * B_PITCH + b_c[j]) * 4), W2 + off, true);
        }
        CP_COMMIT();
    };

    issue(0, 0);
    issue(1, BK);

    for (int kt = 0; kt < KT; kt++) {
        CP_WAIT1();
        __syncthreads();
        if (kt + 2 < KT) issue((kt + 2) % STAGES, (kt + 2) * BK);
        else             CP_COMMIT();

        int st = kt % STAGES;
        const uint32_t* Ac = As + st * A_STAGE;
        const uint32_t* Bc = Bs + st * B_STAGE;

#pragma unroll
        for (int kk = 0; kk < BK; kk += 8) {
            uint32_t ahi[2][4], alo[2][4];
#pragma unroll
            for (int mt = 0; mt < 2; mt++) {
                int r = wm + mt * 16 + (lane >> 2);
                int c = kk + (lane & 3);
                split_tf32(__uint_as_float(Ac[r * A_PITCH + c]),           ahi[mt][0], alo[mt][0]);
                split_tf32(__uint_as_float(Ac[(r + 8) * A_PITCH + c]),     ahi[mt][1], alo[mt][1]);
                split_tf32(__uint_as_float(Ac[r * A_PITCH + c + 4]),       ahi[mt][2], alo[mt][2]);
                split_tf32(__uint_as_float(Ac[(r + 8) * A_PITCH + c + 4]), ahi[mt][3], alo[mt][3]);
            }
#pragma unroll
            for (int nt = 0; nt < 4; nt++) {
                int br = kk + (lane & 3);
                int bc = wn + nt * 8 + (lane >> 2);
                uint32_t bh0, bl0, bh1, bl1;
                split_tf32(__uint_as_float(Bc[br * B_PITCH + bc]),       bh0, bl0);
                split_tf32(__uint_as_float(Bc[(br + 4) * B_PITCH + bc]), bh1, bl1);
#pragma unroll
                for (int mt = 0; mt < 2; mt++) {
                    mma_tf32(acc[mt][nt], ahi[mt], bh0, bh1);
                    mma_tf32(acc[mt][nt], alo[mt], bh0, bh1);
                    mma_tf32(acc[mt][nt], ahi[mt], bl0, bl1);
                }
            }
        }
    }

#pragma unroll
    for (int mt = 0; mt < 2; mt++) {
#pragma unroll
        for (int nt = 0; nt < 4; nt++) {
            int r0 = wm + mt * 16 + (lane >> 2);
            int col = n0 + wn + nt * 8 + (lane & 3) * 2;
#pragma unroll
            for (int half = 0; half < 2; half++) {
                int r = r0 + half * 8;
                int t = s_tok[r];
                if (t >= 0) {
                    atomicAdd(&out[(size_t)t * DDIM + col + 0], acc[mt][nt][half * 2 + 0]);
                    atomicAdd(&out[(size_t)t * DDIM + col + 1], acc[mt][nt][half * 2 + 1]);
                }
            }
        }
    }
}

// ---------------- launch ----------------
extern "C" void kernel_launch(void* const* d_in, const int* in_sizes, int n_in,
                              void* d_out, int out_size) {
    const float* x  = (const float*)d_in[0];
    const float* gw = (const float*)d_in[1];
    const float* w1 = (const float*)d_in[2];
    const float* w2 = (const float*)d_in[3];
    const float* w3 = (const float*)d_in[4];
    float* out = (float*)d_out;

    cudaFuncSetAttribute(gemm13_kernel, cudaFuncAttributeMaxDynamicSharedMemorySize, G13_SMEM_BYTES);
    cudaFuncSetAttribute(gemm2_kernel,  cudaFuncAttributeMaxDynamicSharedMemorySize, G2_SMEM_BYTES);

    cudaMemsetAsync(out, 0, (size_t)out_size * sizeof(float), 0);
    zero_counts_kernel<<<1, 32>>>();
    gate_kernel<<<T_TOK / 8, 256>>>(x, gw);
    scan_kernel<<<1, 1>>>();
    place_kernel<<<(T_TOK + 255) / 256, 256>>>();
    gemm13_kernel<<<dim3(FDIM / BN, T_TOK / BM, NEXP), 256, G13_SMEM_BYTES>>>(x, w1, w3);
    gemm2_kernel<<<dim3(DDIM / BN, T_TOK / BM, NEXP), 256, G2_SMEM_BYTES>>>(w2, out);
}

// round 13
// speedup vs baseline: 1.2620x; 1.2620x over previous
#include <cuda_runtime.h>
#include <cstdint>

#define T_TOK 8192
#define DDIM  1024
#define FDIM  4096
#define NEXP  8

#define BM 128
#define BN 64
#define BK 32
#define STAGES 3          // gemm2 pipeline depth
#define G13_STAGES 2      // gemm13 pipeline depth (2 CTAs/SM)

#define A_PITCH (BK + 4)      // 36 words; conflict-free A-fragment banks
#define B_PITCH (BN + 8)      // 72 words; conflict-free B-fragment banks
#define A_STAGE (BM * A_PITCH)
#define B_STAGE (BK * B_PITCH)

// ---------------- scratch (no allocations allowed) ----------------
__device__ int   g_counts[NEXP];
__device__ int   g_offsets[NEXP];
__device__ int   g_cur[NEXP];
__device__ int   g_top_idx[T_TOK * 2];
__device__ float g_top_w[T_TOK * 2];
__device__ int   g_slot_tok[T_TOK * 2];
__device__ float g_slot_w[T_TOK * 2];
__device__ float g_h[(size_t)T_TOK * 2 * FDIM];   // 268 MB hidden scratch (tf32-valued)

// ---------------- helpers ----------------
__device__ __forceinline__ void mma_tf32(float* c, const uint32_t* a, uint32_t b0, uint32_t b1) {
    asm volatile(
        "mma.sync.aligned.m16n8k8.row.col.f32.tf32.tf32.f32 "
        "{%0,%1,%2,%3}, {%4,%5,%6,%7}, {%8,%9}, {%0,%1,%2,%3};\n"
        : "+f"(c[0]), "+f"(c[1]), "+f"(c[2]), "+f"(c[3])
        : "r"(a[0]), "r"(a[1]), "r"(a[2]), "r"(a[3]), "r"(b0), "r"(b1));
}

// 3xTF32 split: x = hi + lo; residual via explicit sub.rn (Sterbenz-exact).
__device__ __forceinline__ void split_tf32(float x, uint32_t& hi, uint32_t& lo) {
    asm("cvt.rna.tf32.f32 %0, %1;" : "=r"(hi) : "f"(x));
    float r;
    asm("sub.rn.f32 %0, %1, %2;" : "=f"(r) : "f"(x), "f"(__uint_as_float(hi)));
    asm("cvt.rna.tf32.f32 %0, %1;" : "=r"(lo) : "f"(r));
}

__device__ __forceinline__ float round_tf32(float x) {
    uint32_t r;
    asm("cvt.rna.tf32.f32 %0, %1;" : "=r"(r) : "f"(x));
    return __uint_as_float(r);
}

__device__ __forceinline__ void cp16(uint32_t dst, const void* src, bool valid) {
    int sz = valid ? 16 : 0;
    asm volatile("cp.async.cg.shared.global [%0], [%1], 16, %2;\n"
                 :: "r"(dst), "l"(src), "r"(sz));
}
#define CP_COMMIT() asm volatile("cp.async.commit_group;\n" ::: "memory")
#define CP_WAIT1()  asm volatile("cp.async.wait_group 1;\n" ::: "memory")

// ---------------- gating ----------------
__global__ void gate_kernel(const float* __restrict__ x, const float* __restrict__ gw) {
    int warp = (blockIdx.x * blockDim.x + threadIdx.x) >> 5;
    int lane = threadIdx.x & 31;
    if (warp >= T_TOK) return;
    const float* xr = x + (size_t)warp * DDIM;

    float acc[NEXP];
#pragma unroll
    for (int e = 0; e < NEXP; e++) acc[e] = 0.f;

    for (int i = lane; i < DDIM; i += 32) {
        float xv = xr[i];
        const float* g = gw + i * NEXP;
#pragma unroll
        for (int e = 0; e < NEXP; e++) acc[e] += xv * g[e];
    }
#pragma unroll
    for (int e = 0; e < NEXP; e++) {
#pragma unroll
        for (int o = 16; o > 0; o >>= 1) acc[e] += __shfl_xor_sync(0xFFFFFFFFu, acc[e], o);
    }
    if (lane == 0) {
        int i0 = 0; float l0 = acc[0];
#pragma unroll
        for (int e = 1; e < NEXP; e++) if (acc[e] > l0) { l0 = acc[e]; i0 = e; }
        int i1 = -1; float l1 = -1e30f;
#pragma unroll
        for (int e = 0; e < NEXP; e++) if (e != i0 && acc[e] > l1) { l1 = acc[e]; i1 = e; }
        float w0 = 1.f / (1.f + __expf(l1 - l0));
        float w1 = 1.f - w0;
        g_top_idx[2 * warp + 0] = i0;
        g_top_idx[2 * warp + 1] = i1;
        g_top_w[2 * warp + 0] = w0;
        g_top_w[2 * warp + 1] = w1;
    }
}

// counts + prefix in one launch
__global__ void scan_count_kernel() {
    __shared__ int cnt[NEXP];
    int tid = threadIdx.x;
    if (tid < NEXP) cnt[tid] = 0;
    __syncthreads();
    for (int i = tid; i < T_TOK * 2; i += 256)
        atomicAdd(&cnt[g_top_idx[i]], 1);
    __syncthreads();
    if (tid == 0) {
        int s = 0;
        for (int e = 0; e < NEXP; e++) {
            g_counts[e] = cnt[e];
            g_offsets[e] = s;
            g_cur[e] = s;
            s += cnt[e];
        }
    }
}

__global__ void place_kernel() {
    int t = blockIdx.x * blockDim.x + threadIdx.x;
    if (t >= T_TOK) return;
#pragma unroll
    for (int k = 0; k < 2; k++) {
        int e = g_top_idx[2 * t + k];
        int slot = atomicAdd(&g_cur[e], 1);
        g_slot_tok[slot] = t;
        g_slot_w[slot] = g_top_w[2 * t + k];
    }
}

// ---------------- Phase A: h = silu(X@w1)*(X@w3) * route_w ----------------
// 2-stage pipeline -> 73.7 KB smem -> 2 CTAs/SM
#define G13_SMEM_BYTES ((G13_STAGES * (A_STAGE + 2 * B_STAGE)) * 4 + BM * 8)

__global__ void __launch_bounds__(256, 2) gemm13_kernel(const float* __restrict__ x,
                                                        const float* __restrict__ w1,
                                                        const float* __restrict__ w3) {
    int e = blockIdx.z;
    int count = g_counts[e];
    int m0 = blockIdx.y * BM;
    if (m0 >= count) return;
    int base = g_offsets[e];
    int n0 = blockIdx.x * BN;

    extern __shared__ uint32_t sm[];
    uint32_t* As = sm;                                   // G13_STAGES * A_STAGE
    uint32_t* B1 = sm + G13_STAGES * A_STAGE;            // G13_STAGES * B_STAGE
    uint32_t* B3 = B1 + G13_STAGES * B_STAGE;            // G13_STAGES * B_STAGE
    int*   s_tok = (int*)(B3 + G13_STAGES * B_STAGE);
    float* s_w   = (float*)(s_tok + BM);

    uint32_t sa_As = (uint32_t)__cvta_generic_to_shared(As);
    uint32_t sa_B1 = (uint32_t)__cvta_generic_to_shared(B1);
    uint32_t sa_B3 = (uint32_t)__cvta_generic_to_shared(B3);

    int tid = threadIdx.x;
    int lane = tid & 31;
    int wid = tid >> 5;
    int wm = (wid >> 1) * 32;
    int wn = (wid & 1) * 32;

    if (tid < BM) {
        int m = m0 + tid;
        if (m < count) {
            s_tok[tid] = g_slot_tok[base + m];
            s_w[tid] = g_slot_w[base + m];
        } else {
            s_tok[tid] = -1;
            s_w[tid] = 0.f;
        }
    }
    __syncthreads();

    const float* W1 = w1 + (size_t)e * DDIM * FDIM;
    const float* W3 = w3 + (size_t)e * DDIM * FDIM;

    int a_row[4], a_kk[4], a_tok[4];
#pragma unroll
    for (int j = 0; j < 4; j++) {
        int cid = tid + j * 256;
        a_row[j] = cid >> 3;
        a_kk[j] = (cid & 7) * 4;
        a_tok[j] = s_tok[a_row[j]];
    }
    int b_r[2], b_c[2];
#pragma unroll
    for (int j = 0; j < 2; j++) {
        int cid = tid + j * 256;
        b_r[j] = cid >> 4;
        b_c[j] = (cid & 15) * 4;
    }

    float acc1[2][4][4];
    float acc2[2][4][4];
#pragma unroll
    for (int mt = 0; mt < 2; mt++)
#pragma unroll
        for (int nt = 0; nt < 4; nt++)
#pragma unroll
            for (int i = 0; i < 4; i++) { acc1[mt][nt][i] = 0.f; acc2[mt][nt][i] = 0.f; }

    const int KT = DDIM / BK;

    auto issue = [&](int s, int k0) {
#pragma unroll
        for (int j = 0; j < 4; j++) {
            int t = a_tok[j];
            const float* src = (t >= 0) ? x + (size_t)t * DDIM + k0 + a_kk[j] : x;
            cp16(sa_As + (uint32_t)((s * A_STAGE + a_row[j] * A_PITCH + a_kk[j]) * 4), src, t >= 0);
        }
#pragma unroll
        for (int j = 0; j < 2; j++) {
            size_t off = (size_t)(k0 + b_r[j]) * FDIM + n0 + b_c[j];
            uint32_t sd = (uint32_t)((s * B_STAGE + b_r[j] * B_PITCH + b_c[j]) * 4);
            cp16(sa_B1 + sd, W1 + off, true);
            cp16(sa_B3 + sd, W3 + off, true);
        }
        CP_COMMIT();
    };

    issue(0, 0);
    issue(1, BK);

    for (int kt = 0; kt < KT; kt++) {
        CP_WAIT1();            // own groups drained up to stage kt (kt+1 pending)
        __syncthreads();       // stage kt writes from ALL threads visible

        int st = kt & 1;
        const uint32_t* Ac = As + st * A_STAGE;
        const uint32_t* B1c = B1 + st * B_STAGE;
        const uint32_t* B3c = B3 + st * B_STAGE;

#pragma unroll
        for (int kk = 0; kk < BK; kk += 8) {
            uint32_t ahi[2][4], alo[2][4];
#pragma unroll
            for (int mt = 0; mt < 2; mt++) {
                int r = wm + mt * 16 + (lane >> 2);
                int c = kk + (lane & 3);
                split_tf32(__uint_as_float(Ac[r * A_PITCH + c]),           ahi[mt][0], alo[mt][0]);
                split_tf32(__uint_as_float(Ac[(r + 8) * A_PITCH + c]),     ahi[mt][1], alo[mt][1]);
                split_tf32(__uint_as_float(Ac[r * A_PITCH + c + 4]),       ahi[mt][2], alo[mt][2]);
                split_tf32(__uint_as_float(Ac[(r + 8) * A_PITCH + c + 4]), ahi[mt][3], alo[mt][3]);
            }
#pragma unroll
            for (int nt = 0; nt < 4; nt++) {
                int br = kk + (lane & 3);
                int bc = wn + nt * 8 + (lane >> 2);
                uint32_t b1h0, b1l0, b1h1, b1l1, b3h0, b3l0, b3h1, b3l1;
                split_tf32(__uint_as_float(B1c[br * B_PITCH + bc]),       b1h0, b1l0);
                split_tf32(__uint_as_float(B1c[(br + 4) * B_PITCH + bc]), b1h1, b1l1);
                split_tf32(__uint_as_float(B3c[br * B_PITCH + bc]),       b3h0, b3l0);
                split_tf32(__uint_as_float(B3c[(br + 4) * B_PITCH + bc]), b3h1, b3l1);
#pragma unroll
                for (int mt = 0; mt < 2; mt++) {
                    mma_tf32(acc1[mt][nt], ahi[mt], b1h0, b1h1);
                    mma_tf32(acc1[mt][nt], alo[mt], b1h0, b1h1);
                    mma_tf32(acc1[mt][nt], ahi[mt], b1l0, b1l1);
                    mma_tf32(acc2[mt][nt], ahi[mt], b3h0, b3h1);
                    mma_tf32(acc2[mt][nt], alo[mt], b3h0, b3h1);
                    mma_tf32(acc2[mt][nt], ahi[mt], b3l0, b3l1);
                }
            }
        }

        __syncthreads();       // all warps done reading buffer kt&1
        if (kt + 2 < KT) issue((kt + 2) & 1, (kt + 2) * BK);   // refill same buffer: safe
        else             CP_COMMIT();                          // keep group count uniform
    }

    // epilogue: SwiGLU * routing weight -> g_h, ROUNDED TO TF32.
    // gemm2 consumes g_h as its A operand: tf32-valued input means its split
    // residual is exactly zero, so gemm2 runs a 2-term MMA legally.
#pragma unroll
    for (int mt = 0; mt < 2; mt++) {
#pragma unroll
        for (int nt = 0; nt < 4; nt++) {
            int r0 = wm + mt * 16 + (lane >> 2);
            int col = n0 + wn + nt * 8 + (lane & 3) * 2;
#pragma unroll
            for (int half = 0; half < 2; half++) {
                int r = r0 + half * 8;
                int m = m0 + r;
                if (m < count) {
                    float u0 = acc1[mt][nt][half * 2 + 0];
                    float u1 = acc1[mt][nt][half * 2 + 1];
                    float v0 = acc2[mt][nt][half * 2 + 0];
                    float v1 = acc2[mt][nt][half * 2 + 1];
                    float wr = s_w[r];
                    float h0 = round_tf32((u0 / (1.f + __expf(-u0))) * v0 * wr);
                    float h1 = round_tf32((u1 / (1.f + __expf(-u1))) * v1 * wr);
                    float2* p = (float2*)(g_h + (size_t)(base + m) * FDIM + col);
                    *p = make_float2(h0, h1);
                }
            }
        }
    }
}

// ---------------- Phase B: out += h @ w2 (atomic scatter) ----------------
// A operand (g_h) is tf32-valued -> no A split, 2 MMAs per accumulator.
#define G2_SMEM_BYTES ((STAGES * (A_STAGE + B_STAGE)) * 4 + BM * 4)

__global__ void __launch_bounds__(256, 2) gemm2_kernel(const float* __restrict__ w2,
                                                       float* __restrict__ out) {
    int e = blockIdx.z;
    int count = g_counts[e];
    int m0 = blockIdx.y * BM;
    if (m0 >= count) return;
    int base = g_offsets[e];
    int n0 = blockIdx.x * BN;

    extern __shared__ uint32_t sm[];
    uint32_t* As = sm;
    uint32_t* Bs = sm + STAGES * A_STAGE;
    int* s_tok = (int*)(Bs + STAGES * B_STAGE);

    uint32_t sa_As = (uint32_t)__cvta_generic_to_shared(As);
    uint32_t sa_Bs = (uint32_t)__cvta_generic_to_shared(Bs);

    int tid = threadIdx.x;
    int lane = tid & 31;
    int wid = tid >> 5;
    int wm = (wid >> 1) * 32;
    int wn = (wid & 1) * 32;

    if (tid < BM) {
        int m = m0 + tid;
        s_tok[tid] = (m < count) ? g_slot_tok[base + m] : -1;
    }
    __syncthreads();

    const float* W2 = w2 + (size_t)e * FDIM * DDIM;

    int a_row[4], a_kk[4]; bool a_ok[4];
#pragma unroll
    for (int j = 0; j < 4; j++) {
        int cid = tid + j * 256;
        a_row[j] = cid >> 3;
        a_kk[j] = (cid & 7) * 4;
        a_ok[j] = (m0 + a_row[j]) < count;
    }
    int b_r[2], b_c[2];
#pragma unroll
    for (int j = 0; j < 2; j++) {
        int cid = tid + j * 256;
        b_r[j] = cid >> 4;
        b_c[j] = (cid & 15) * 4;
    }

    float acc[2][4][4];
#pragma unroll
    for (int mt = 0; mt < 2; mt++)
#pragma unroll
        for (int nt = 0; nt < 4; nt++)
#pragma unroll
            for (int i = 0; i < 4; i++) acc[mt][nt][i] = 0.f;

    const int KT = FDIM / BK;

    auto issue = [&](int s, int k0) {
#pragma unroll
        for (int j = 0; j < 4; j++) {
            const float* src = g_h + (size_t)(base + m0 + a_row[j]) * FDIM + k0 + a_kk[j];
            cp16(sa_As + (uint32_t)((s * A_STAGE + a_row[j] * A_PITCH + a_kk[j]) * 4),
                 a_ok[j] ? src : (const float*)g_h, a_ok[j]);
        }
#pragma unroll
        for (int j = 0; j < 2; j++) {
            size_t off = (size_t)(k0 + b_r[j]) * DDIM + n0 + b_c[j];
            cp16(sa_Bs + (uint32_t)((s * B_STAGE + b_r[j] * B_PITCH + b_c[j]) * 4), W2 + off, true);
        }
        CP_COMMIT();
    };

    issue(0, 0);
    issue(1, BK);

    for (int kt = 0; kt < KT; kt++) {
        CP_WAIT1();
        __syncthreads();
        if (kt + 2 < KT) issue((kt + 2) % STAGES, (kt + 2) * BK);
        else             CP_COMMIT();

        int st = kt % STAGES;
        const uint32_t* Ac = As + st * A_STAGE;
        const uint32_t* Bc = Bs + st * B_STAGE;

#pragma unroll
        for (int kk = 0; kk < BK; kk += 8) {
            uint32_t a[2][4];                 // tf32-valued: no split needed
#pragma unroll
            for (int mt = 0; mt < 2; mt++) {
                int r = wm + mt * 16 + (lane >> 2);
                int c = kk + (lane & 3);
                a[mt][0] = Ac[r * A_PITCH + c];
                a[mt][1] = Ac[(r + 8) * A_PITCH + c];
                a[mt][2] = Ac[r * A_PITCH + c + 4];
                a[mt][3] = Ac[(r + 8) * A_PITCH + c + 4];
            }
#pragma unroll
            for (int nt = 0; nt < 4; nt++) {
                int br = kk + (lane & 3);
                int bc = wn + nt * 8 + (lane >> 2);
                uint32_t bh0, bl0, bh1, bl1;
                split_tf32(__uint_as_float(Bc[br * B_PITCH + bc]),       bh0, bl0);
                split_tf32(__uint_as_float(Bc[(br + 4) * B_PITCH + bc]), bh1, bl1);
#pragma unroll
                for (int mt = 0; mt < 2; mt++) {
                    mma_tf32(acc[mt][nt], a[mt], bh0, bh1);
                    mma_tf32(acc[mt][nt], a[mt], bl0, bl1);
                }
            }
        }
    }

#pragma unroll
    for (int mt = 0; mt < 2; mt++) {
#pragma unroll
        for (int nt = 0; nt < 4; nt++) {
            int r0 = wm + mt * 16 + (lane >> 2);
            int col = n0 + wn + nt * 8 + (lane & 3) * 2;
#pragma unroll
            for (int half = 0; half < 2; half++) {
                int r = r0 + half * 8;
                int t = s_tok[r];
                if (t >= 0) {
                    atomicAdd(&out[(size_t)t * DDIM + col + 0], acc[mt][nt][half * 2 + 0]);
                    atomicAdd(&out[(size_t)t * DDIM + col + 1], acc[mt][nt][half * 2 + 1]);
                }
            }
        }
    }
}

// ---------------- launch ----------------
extern "C" void kernel_launch(void* const* d_in, const int* in_sizes, int n_in,
                              void* d_out, int out_size) {
    const float* x  = (const float*)d_in[0];
    const float* gw = (const float*)d_in[1];
    const float* w1 = (const float*)d_in[2];
    const float* w2 = (const float*)d_in[3];
    const float* w3 = (const float*)d_in[4];
    float* out = (float*)d_out;

    cudaFuncSetAttribute(gemm13_kernel, cudaFuncAttributeMaxDynamicSharedMemorySize, G13_SMEM_BYTES);
    cudaFuncSetAttribute(gemm2_kernel,  cudaFuncAttributeMaxDynamicSharedMemorySize, G2_SMEM_BYTES);

    cudaMemsetAsync(out, 0, (size_t)out_size * sizeof(float), 0);
    gate_kernel<<<T_TOK / 8, 256>>>(x, gw);
    scan_count_kernel<<<1, 256>>>();
    place_kernel<<<(T_TOK + 255) / 256, 256>>>();
    gemm13_kernel<<<dim3(FDIM / BN, T_TOK / BM, NEXP), 256, G13_SMEM_BYTES>>>(x, w1, w3);
    gemm2_kernel<<<dim3(DDIM / BN, T_TOK / BM, NEXP), 256, G2_SMEM_BYTES>>>(w2, out);
}

// round 14
// speedup vs baseline: 1.5709x; 1.2448x over previous
#include <cuda_runtime.h>
#include <cstdint>

#define T_TOK 8192
#define DDIM  1024
#define FDIM  4096
#define NEXP  8

#define BM 128
#define BN 64
#define BK 32
#define STAGES 3          // gemm2 pipeline depth
#define G13_STAGES 2      // gemm13 pipeline depth (2 CTAs/SM)

#define A_PITCH (BK + 4)      // 36 words; conflict-free A-fragment banks
#define B_PITCH (BN + 8)      // 72 words; conflict-free B-fragment banks
#define A_STAGE (BM * A_PITCH)
#define B_STAGE (BK * B_PITCH)

// ---------------- scratch (no allocations allowed) ----------------
__device__ int   g_counts[NEXP];
__device__ int   g_offsets[NEXP];
__device__ int   g_cur[NEXP];
__device__ int   g_top_idx[T_TOK * 2];
__device__ float g_top_w[T_TOK * 2];
__device__ int   g_slot_tok[T_TOK * 2];
__device__ float g_slot_w[T_TOK * 2];
__device__ float g_h[(size_t)T_TOK * 2 * FDIM];   // 268 MB hidden scratch (tf32-valued)

// ---------------- helpers ----------------
__device__ __forceinline__ void mma_tf32(float* c, const uint32_t* a, uint32_t b0, uint32_t b1) {
    asm volatile(
        "mma.sync.aligned.m16n8k8.row.col.f32.tf32.tf32.f32 "
        "{%0,%1,%2,%3}, {%4,%5,%6,%7}, {%8,%9}, {%0,%1,%2,%3};\n"
        : "+f"(c[0]), "+f"(c[1]), "+f"(c[2]), "+f"(c[3])
        : "r"(a[0]), "r"(a[1]), "r"(a[2]), "r"(a[3]), "r"(b0), "r"(b1));
}

// 3xTF32 split: x = hi + lo; residual via explicit sub.rn (Sterbenz-exact).
__device__ __forceinline__ void split_tf32(float x, uint32_t& hi, uint32_t& lo) {
    asm("cvt.rna.tf32.f32 %0, %1;" : "=r"(hi) : "f"(x));
    float r;
    asm("sub.rn.f32 %0, %1, %2;" : "=f"(r) : "f"(x), "f"(__uint_as_float(hi)));
    asm("cvt.rna.tf32.f32 %0, %1;" : "=r"(lo) : "f"(r));
}

__device__ __forceinline__ uint32_t cvt_tf32(float x) {
    uint32_t r;
    asm("cvt.rna.tf32.f32 %0, %1;" : "=r"(r) : "f"(x));
    return r;
}

__device__ __forceinline__ float round_tf32(float x) {
    return __uint_as_float(cvt_tf32(x));
}

__device__ __forceinline__ void cp16(uint32_t dst, const void* src, bool valid) {
    int sz = valid ? 16 : 0;
    asm volatile("cp.async.cg.shared.global [%0], [%1], 16, %2;\n"
                 :: "r"(dst), "l"(src), "r"(sz));
}
#define CP_COMMIT() asm volatile("cp.async.commit_group;\n" ::: "memory")
#define CP_WAIT1()  asm volatile("cp.async.wait_group 1;\n" ::: "memory")

// ---------------- gating ----------------
__global__ void gate_kernel(const float* __restrict__ x, const float* __restrict__ gw) {
    int warp = (blockIdx.x * blockDim.x + threadIdx.x) >> 5;
    int lane = threadIdx.x & 31;
    if (warp >= T_TOK) return;
    const float* xr = x + (size_t)warp * DDIM;

    float acc[NEXP];
#pragma unroll
    for (int e = 0; e < NEXP; e++) acc[e] = 0.f;

    for (int i = lane; i < DDIM; i += 32) {
        float xv = xr[i];
        const float* g = gw + i * NEXP;
#pragma unroll
        for (int e = 0; e < NEXP; e++) acc[e] += xv * g[e];
    }
#pragma unroll
    for (int e = 0; e < NEXP; e++) {
#pragma unroll
        for (int o = 16; o > 0; o >>= 1) acc[e] += __shfl_xor_sync(0xFFFFFFFFu, acc[e], o);
    }
    if (lane == 0) {
        int i0 = 0; float l0 = acc[0];
#pragma unroll
        for (int e = 1; e < NEXP; e++) if (acc[e] > l0) { l0 = acc[e]; i0 = e; }
        int i1 = -1; float l1 = -1e30f;
#pragma unroll
        for (int e = 0; e < NEXP; e++) if (e != i0 && acc[e] > l1) { l1 = acc[e]; i1 = e; }
        float w0 = 1.f / (1.f + __expf(l1 - l0));
        float w1 = 1.f - w0;
        g_top_idx[2 * warp + 0] = i0;
        g_top_idx[2 * warp + 1] = i1;
        g_top_w[2 * warp + 0] = w0;
        g_top_w[2 * warp + 1] = w1;
    }
}

// counts + prefix in one launch
__global__ void scan_count_kernel() {
    __shared__ int cnt[NEXP];
    int tid = threadIdx.x;
    if (tid < NEXP) cnt[tid] = 0;
    __syncthreads();
    for (int i = tid; i < T_TOK * 2; i += 256)
        atomicAdd(&cnt[g_top_idx[i]], 1);
    __syncthreads();
    if (tid == 0) {
        int s = 0;
        for (int e = 0; e < NEXP; e++) {
            g_counts[e] = cnt[e];
            g_offsets[e] = s;
            g_cur[e] = s;
            s += cnt[e];
        }
    }
}

__global__ void place_kernel() {
    int t = blockIdx.x * blockDim.x + threadIdx.x;
    if (t >= T_TOK) return;
#pragma unroll
    for (int k = 0; k < 2; k++) {
        int e = g_top_idx[2 * t + k];
        int slot = atomicAdd(&g_cur[e], 1);
        g_slot_tok[slot] = t;
        g_slot_w[slot] = g_top_w[2 * t + k];
    }
}

// ---------------- Phase A: h = silu(X@w1)*(X@w3) * route_w ----------------
// 2-stage pipeline -> 73.7 KB smem -> 2 CTAs/SM.
// A (x) is tf32-ROUNDED in fragments: no A split, 4 MMAs per (mt,nt) pair.
#define G13_SMEM_BYTES ((G13_STAGES * (A_STAGE + 2 * B_STAGE)) * 4 + BM * 8)

__global__ void __launch_bounds__(256, 2) gemm13_kernel(const float* __restrict__ x,
                                                        const float* __restrict__ w1,
                                                        const float* __restrict__ w3) {
    int e = blockIdx.z;
    int count = g_counts[e];
    int m0 = blockIdx.y * BM;
    if (m0 >= count) return;
    int base = g_offsets[e];
    int n0 = blockIdx.x * BN;

    extern __shared__ uint32_t sm[];
    uint32_t* As = sm;                                   // G13_STAGES * A_STAGE
    uint32_t* B1 = sm + G13_STAGES * A_STAGE;            // G13_STAGES * B_STAGE
    uint32_t* B3 = B1 + G13_STAGES * B_STAGE;            // G13_STAGES * B_STAGE
    int*   s_tok = (int*)(B3 + G13_STAGES * B_STAGE);
    float* s_w   = (float*)(s_tok + BM);

    uint32_t sa_As = (uint32_t)__cvta_generic_to_shared(As);
    uint32_t sa_B1 = (uint32_t)__cvta_generic_to_shared(B1);
    uint32_t sa_B3 = (uint32_t)__cvta_generic_to_shared(B3);

    int tid = threadIdx.x;
    int lane = tid & 31;
    int wid = tid >> 5;
    int wm = (wid >> 1) * 32;
    int wn = (wid & 1) * 32;

    if (tid < BM) {
        int m = m0 + tid;
        if (m < count) {
            s_tok[tid] = g_slot_tok[base + m];
            s_w[tid] = g_slot_w[base + m];
        } else {
            s_tok[tid] = -1;
            s_w[tid] = 0.f;
        }
    }
    __syncthreads();

    const float* W1 = w1 + (size_t)e * DDIM * FDIM;
    const float* W3 = w3 + (size_t)e * DDIM * FDIM;

    int a_row[4], a_kk[4], a_tok[4];
#pragma unroll
    for (int j = 0; j < 4; j++) {
        int cid = tid + j * 256;
        a_row[j] = cid >> 3;
        a_kk[j] = (cid & 7) * 4;
        a_tok[j] = s_tok[a_row[j]];
    }
    int b_r[2], b_c[2];
#pragma unroll
    for (int j = 0; j < 2; j++) {
        int cid = tid + j * 256;
        b_r[j] = cid >> 4;
        b_c[j] = (cid & 15) * 4;
    }

    float acc1[2][4][4];
    float acc2[2][4][4];
#pragma unroll
    for (int mt = 0; mt < 2; mt++)
#pragma unroll
        for (int nt = 0; nt < 4; nt++)
#pragma unroll
            for (int i = 0; i < 4; i++) { acc1[mt][nt][i] = 0.f; acc2[mt][nt][i] = 0.f; }

    const int KT = DDIM / BK;

    auto issue = [&](int s, int k0) {
#pragma unroll
        for (int j = 0; j < 4; j++) {
            int t = a_tok[j];
            const float* src = (t >= 0) ? x + (size_t)t * DDIM + k0 + a_kk[j] : x;
            cp16(sa_As + (uint32_t)((s * A_STAGE + a_row[j] * A_PITCH + a_kk[j]) * 4), src, t >= 0);
        }
#pragma unroll
        for (int j = 0; j < 2; j++) {
            size_t off = (size_t)(k0 + b_r[j]) * FDIM + n0 + b_c[j];
            uint32_t sd = (uint32_t)((s * B_STAGE + b_r[j] * B_PITCH + b_c[j]) * 4);
            cp16(sa_B1 + sd, W1 + off, true);
            cp16(sa_B3 + sd, W3 + off, true);
        }
        CP_COMMIT();
    };

    issue(0, 0);
    issue(1, BK);

    for (int kt = 0; kt < KT; kt++) {
        CP_WAIT1();            // own groups drained up to stage kt (kt+1 pending)
        __syncthreads();       // stage kt writes from ALL threads visible

        int st = kt & 1;
        const uint32_t* Ac = As + st * A_STAGE;
        const uint32_t* B1c = B1 + st * B_STAGE;
        const uint32_t* B3c = B3 + st * B_STAGE;

#pragma unroll
        for (int kk = 0; kk < BK; kk += 8) {
            uint32_t a[2][4];          // tf32-rounded x fragments (no split)
#pragma unroll
            for (int mt = 0; mt < 2; mt++) {
                int r = wm + mt * 16 + (lane >> 2);
                int c = kk + (lane & 3);
                a[mt][0] = cvt_tf32(__uint_as_float(Ac[r * A_PITCH + c]));
                a[mt][1] = cvt_tf32(__uint_as_float(Ac[(r + 8) * A_PITCH + c]));
                a[mt][2] = cvt_tf32(__uint_as_float(Ac[r * A_PITCH + c + 4]));
                a[mt][3] = cvt_tf32(__uint_as_float(Ac[(r + 8) * A_PITCH + c + 4]));
            }
#pragma unroll
            for (int nt = 0; nt < 4; nt++) {
                int br = kk + (lane & 3);
                int bc = wn + nt * 8 + (lane >> 2);
                uint32_t b1h0, b1l0, b1h1, b1l1, b3h0, b3l0, b3h1, b3l1;
                split_tf32(__uint_as_float(B1c[br * B_PITCH + bc]),       b1h0, b1l0);
                split_tf32(__uint_as_float(B1c[(br + 4) * B_PITCH + bc]), b1h1, b1l1);
                split_tf32(__uint_as_float(B3c[br * B_PITCH + bc]),       b3h0, b3l0);
                split_tf32(__uint_as_float(B3c[(br + 4) * B_PITCH + bc]), b3h1, b3l1);
#pragma unroll
                for (int mt = 0; mt < 2; mt++) {
                    mma_tf32(acc1[mt][nt], a[mt], b1h0, b1h1);
                    mma_tf32(acc1[mt][nt], a[mt], b1l0, b1l1);
                    mma_tf32(acc2[mt][nt], a[mt], b3h0, b3h1);
                    mma_tf32(acc2[mt][nt], a[mt], b3l0, b3l1);
                }
            }
        }

        __syncthreads();       // all warps done reading buffer kt&1
        if (kt + 2 < KT) issue((kt + 2) & 1, (kt + 2) * BK);   // refill same buffer: safe
        else             CP_COMMIT();                          // keep group count uniform
    }

    // epilogue: SwiGLU * routing weight -> g_h, ROUNDED TO TF32
    // (gemm2's A operand is tf32-valued -> its A-split residual is exactly 0).
#pragma unroll
    for (int mt = 0; mt < 2; mt++) {
#pragma unroll
        for (int nt = 0; nt < 4; nt++) {
            int r0 = wm + mt * 16 + (lane >> 2);
            int col = n0 + wn + nt * 8 + (lane & 3) * 2;
#pragma unroll
            for (int half = 0; half < 2; half++) {
                int r = r0 + half * 8;
                int m = m0 + r;
                if (m < count) {
                    float u0 = acc1[mt][nt][half * 2 + 0];
                    float u1 = acc1[mt][nt][half * 2 + 1];
                    float v0 = acc2[mt][nt][half * 2 + 0];
                    float v1 = acc2[mt][nt][half * 2 + 1];
                    float wr = s_w[r];
                    float h0 = round_tf32((u0 / (1.f + __expf(-u0))) * v0 * wr);
                    float h1 = round_tf32((u1 / (1.f + __expf(-u1))) * v1 * wr);
                    float2* p = (float2*)(g_h + (size_t)(base + m) * FDIM + col);
                    *p = make_float2(h0, h1);
                }
            }
        }
    }
}

// ---------------- Phase B: out += h @ w2 (atomic scatter) ----------------
// A operand (g_h) is tf32-valued -> no A split, 2 MMAs per accumulator.
#define G2_SMEM_BYTES ((STAGES * (A_STAGE + B_STAGE)) * 4 + BM * 4)

__global__ void __launch_bounds__(256, 2) gemm2_kernel(const float* __restrict__ w2,
                                                       float* __restrict__ out) {
    int e = blockIdx.z;
    int count = g_counts[e];
    int m0 = blockIdx.y * BM;
    if (m0 >= count) return;
    int base = g_offsets[e];
    int n0 = blockIdx.x * BN;

    extern __shared__ uint32_t sm[];
    uint32_t* As = sm;
    uint32_t* Bs = sm + STAGES * A_STAGE;
    int* s_tok = (int*)(Bs + STAGES * B_STAGE);

    uint32_t sa_As = (uint32_t)__cvta_generic_to_shared(As);
    uint32_t sa_Bs = (uint32_t)__cvta_generic_to_shared(Bs);

    int tid = threadIdx.x;
    int lane = tid & 31;
    int wid = tid >> 5;
    int wm = (wid >> 1) * 32;
    int wn = (wid & 1) * 32;

    if (tid < BM) {
        int m = m0 + tid;
        s_tok[tid] = (m < count) ? g_slot_tok[base + m] : -1;
    }
    __syncthreads();

    const float* W2 = w2 + (size_t)e * FDIM * DDIM;

    int a_row[4], a_kk[4]; bool a_ok[4];
#pragma unroll
    for (int j = 0; j < 4; j++) {
        int cid = tid + j * 256;
        a_row[j] = cid >> 3;
        a_kk[j] = (cid & 7) * 4;
        a_ok[j] = (m0 + a_row[j]) < count;
    }
    int b_r[2], b_c[2];
#pragma unroll
    for (int j = 0; j < 2; j++) {
        int cid = tid + j * 256;
        b_r[j] = cid >> 4;
        b_c[j] = (cid & 15) * 4;
    }

    float acc[2][4][4];
#pragma unroll
    for (int mt = 0; mt < 2; mt++)
#pragma unroll
        for (int nt = 0; nt < 4; nt++)
#pragma unroll
            for (int i = 0; i < 4; i++) acc[mt][nt][i] = 0.f;

    const int KT = FDIM / BK;

    auto issue = [&](int s, int k0) {
#pragma unroll
        for (int j = 0; j < 4; j++) {
            const float* src = g_h + (size_t)(base + m0 + a_row[j]) * FDIM + k0 + a_kk[j];
            cp16(sa_As + (uint32_t)((s * A_STAGE + a_row[j] * A_PITCH + a_kk[j]) * 4),
                 a_ok[j] ? src : (const float*)g_h, a_ok[j]);
        }
#pragma unroll
        for (int j = 0; j < 2; j++) {
            size_t off = (size_t)(k0 + b_r[j]) * DDIM + n0 + b_c[j];
            cp16(sa_Bs + (uint32_t)((s * B_STAGE + b_r[j] * B_PITCH + b_c[j]) * 4), W2 + off, true);
        }
        CP_COMMIT();
    };

    issue(0, 0);
    issue(1, BK);

    for (int kt = 0; kt < KT; kt++) {
        CP_WAIT1();
        __syncthreads();
        if (kt + 2 < KT) issue((kt + 2) % STAGES, (kt + 2) * BK);
        else             CP_COMMIT();

        int st = kt % STAGES;
        const uint32_t* Ac = As + st * A_STAGE;
        const uint32_t* Bc = Bs + st * B_STAGE;

#pragma unroll
        for (int kk = 0; kk < BK; kk += 8) {
            uint32_t a[2][4];                 // tf32-valued: no split needed
#pragma unroll
            for (int mt = 0; mt < 2; mt++) {
                int r = wm + mt * 16 + (lane >> 2);
                int c = kk + (lane & 3);
                a[mt][0] = Ac[r * A_PITCH + c];
                a[mt][1] = Ac[(r + 8) * A_PITCH + c];
                a[mt][2] = Ac[r * A_PITCH + c + 4];
                a[mt][3] = Ac[(r + 8) * A_PITCH + c + 4];
            }
#pragma unroll
            for (int nt = 0; nt < 4; nt++) {
                int br = kk + (lane & 3);
                int bc = wn + nt * 8 + (lane >> 2);
                uint32_t bh0, bl0, bh1, bl1;
                split_tf32(__uint_as_float(Bc[br * B_PITCH + bc]),       bh0, bl0);
                split_tf32(__uint_as_float(Bc[(br + 4) * B_PITCH + bc]), bh1, bl1);
#pragma unroll
                for (int mt = 0; mt < 2; mt++) {
                    mma_tf32(acc[mt][nt], a[mt], bh0, bh1);
                    mma_tf32(acc[mt][nt], a[mt], bl0, bl1);
                }
            }
        }
    }

#pragma unroll
    for (int mt = 0; mt < 2; mt++) {
#pragma unroll
        for (int nt = 0; nt < 4; nt++) {
            int r0 = wm + mt * 16 + (lane >> 2);
            int col = n0 + wn + nt * 8 + (lane & 3) * 2;
#pragma unroll
            for (int half = 0; half < 2; half++) {
                int r = r0 + half * 8;
                int t = s_tok[r];
                if (t >= 0) {
                    atomicAdd(&out[(size_t)t * DDIM + col + 0], acc[mt][nt][half * 2 + 0]);
                    atomicAdd(&out[(size_t)t * DDIM + col + 1], acc[mt][nt][half * 2 + 1]);
                }
            }
        }
    }
}

// ---------------- launch ----------------
extern "C" void kernel_launch(void* const* d_in, const int* in_sizes, int n_in,
                              void* d_out, int out_size) {
    const float* x  = (const float*)d_in[0];
    const float* gw = (const float*)d_in[1];
    const float* w1 = (const float*)d_in[2];
    const float* w2 = (const float*)d_in[3];
    const float* w3 = (const float*)d_in[4];
    float* out = (float*)d_out;

    cudaFuncSetAttribute(gemm13_kernel, cudaFuncAttributeMaxDynamicSharedMemorySize, G13_SMEM_BYTES);
    cudaFuncSetAttribute(gemm2_kernel,  cudaFuncAttributeMaxDynamicSharedMemorySize, G2_SMEM_BYTES);

    cudaMemsetAsync(out, 0, (size_t)out_size * sizeof(float), 0);
    gate_kernel<<<T_TOK / 8, 256>>>(x, gw);
    scan_count_kernel<<<1, 256>>>();
    place_kernel<<<(T_TOK + 255) / 256, 256>>>();
    gemm13_kernel<<<dim3(FDIM / BN, T_TOK / BM, NEXP), 256, G13_SMEM_BYTES>>>(x, w1, w3);
    gemm2_kernel<<<dim3(DDIM / BN, T_TOK / BM, NEXP), 256, G2_SMEM_BYTES>>>(w2, out);
}